// round 5
// baseline (speedup 1.0000x reference)
#include <cuda_runtime.h>
#include <cuda_fp16.h>
#include <math.h>

#define B_    32
#define CIN   3
#define HIN   224
#define WIN   224
#define CO    192
#define OH    112
#define OW    112
#define PH    56
#define PW    56
#define NPC   (B_*OH*OW)   // 401408

// -------- device scratch ----------------------------------------------------
__device__ __half g_yh[(size_t)B_*CO*OH*OW];   // conv output fp16, ~154 MB
__device__ float g_sum[CO];                    // zero-initialized at load;
__device__ float g_sq[CO];                     // finalize re-zeroes each iter
__device__ float g_scale[CO];
__device__ float g_shift[CO];

// ---------------------------------------------------------------------------
// Conv + stats. 256 thr = 8 warps. Warp -> 4 channels (weights warp-uniform,
// float4 broadcast LDS). Lane -> 2 output cols. Tile: 2 output rows.
// Small per-thread state (16 fp32 acc) -> <=64 regs -> 4 blocks/SM, 32 warps.
#define CONV_THREADS 256
#define IN_ROWS  5
#define IN_COLS  132
#define SIN_SZ   (CIN*IN_ROWS*IN_COLS)   // 1980 floats
#define SW_SZ    (27*32)                 // 864 floats

__global__ __launch_bounds__(CONV_THREADS, 4)
void conv_stats_kernel(const float* __restrict__ x,
                       const float* __restrict__ conv_w,
                       const float* __restrict__ conv_b) {
    extern __shared__ float smem[];
    float* sIn = smem;              // [ci][5][132]
    float* sW  = smem + SIN_SZ;     // [tap][ch_local 0..31]

    const int tid  = threadIdx.x;
    const int lane = tid & 31;
    const int wrp  = tid >> 5;

    const int ct = blockIdx.x & 1;       // col tile (0: 64 cols, 1: 48 cols)
    const int rt = blockIdx.x >> 1;      // 2-row tile, 0..55
    const int b  = blockIdx.y;
    const int cz = blockIdx.z;           // 32-channel group

    const int c0     = ct * 64;
    const bool active = (2*lane) < (ct ? 48 : 64);

    // ---- load input tile (zero padded) ----
    const int rowbase = 4*rt - 1;
    const int colbase = 2*c0 - 1;
    for (int idx = tid; idx < SIN_SZ; idx += CONV_THREADS) {
        int ci  = idx / (IN_ROWS*IN_COLS);
        int rem = idx - ci*(IN_ROWS*IN_COLS);
        int r   = rem / IN_COLS;
        int col = rem - r*IN_COLS;
        int gr = rowbase + r;
        int gc = colbase + col;
        float v = 0.f;
        if (gr >= 0 && gr < HIN && gc >= 0 && gc < WIN)
            v = x[((size_t)(b*CIN + ci)*HIN + gr)*WIN + gc];
        sIn[idx] = v;
    }
    for (int idx = tid; idx < SW_SZ; idx += CONV_THREADS) {
        int tap = idx >> 5;
        int cl  = idx & 31;
        sW[idx] = conv_w[(cz*32 + cl)*27 + tap];
    }
    __syncthreads();

    const int cbase = cz*32 + wrp*4;
    const float4* sW4 = (const float4*)sW;   // sW4[tap*8 + wrp]

    float4 bv = *(const float4*)&conv_b[cbase];
    // acc[oy][col][ch]
    float acc[2][2][4];
    #pragma unroll
    for (int oy = 0; oy < 2; ++oy)
        #pragma unroll
        for (int q = 0; q < 2; ++q) {
            acc[oy][q][0] = bv.x; acc[oy][q][1] = bv.y;
            acc[oy][q][2] = bv.z; acc[oy][q][3] = bv.w;
        }

    #pragma unroll
    for (int ci = 0; ci < 3; ++ci) {
        const float* iprow = &sIn[ci*(IN_ROWS*IN_COLS) + 4*lane];
        #pragma unroll
        for (int ky = 0; ky < 3; ++ky) {
            const int tb = (ci*9 + ky*3)*8 + wrp;
            float4 w0 = sW4[tb];        // kx=0, 4 channels (warp-uniform)
            float4 w1 = sW4[tb + 8];    // kx=1
            float4 w2 = sW4[tb + 16];   // kx=2
            #pragma unroll
            for (int oy = 0; oy < 2; ++oy) {
                const float* ip = iprow + (2*oy + ky)*IN_COLS;
                float4 a = *(const float4*)ip;
                float e = __shfl_down_sync(0xffffffffu, a.x, 1);
                if (lane == 31) e = ip[4];
                // col0 uses a.x,a.y,a.z ; col1 uses a.z,a.w,e
                acc[oy][0][0] = fmaf(w0.x, a.x, acc[oy][0][0]);
                acc[oy][0][1] = fmaf(w0.y, a.x, acc[oy][0][1]);
                acc[oy][0][2] = fmaf(w0.z, a.x, acc[oy][0][2]);
                acc[oy][0][3] = fmaf(w0.w, a.x, acc[oy][0][3]);
                acc[oy][1][0] = fmaf(w0.x, a.z, acc[oy][1][0]);
                acc[oy][1][1] = fmaf(w0.y, a.z, acc[oy][1][1]);
                acc[oy][1][2] = fmaf(w0.z, a.z, acc[oy][1][2]);
                acc[oy][1][3] = fmaf(w0.w, a.z, acc[oy][1][3]);
                acc[oy][0][0] = fmaf(w1.x, a.y, acc[oy][0][0]);
                acc[oy][0][1] = fmaf(w1.y, a.y, acc[oy][0][1]);
                acc[oy][0][2] = fmaf(w1.z, a.y, acc[oy][0][2]);
                acc[oy][0][3] = fmaf(w1.w, a.y, acc[oy][0][3]);
                acc[oy][1][0] = fmaf(w1.x, a.w, acc[oy][1][0]);
                acc[oy][1][1] = fmaf(w1.y, a.w, acc[oy][1][1]);
                acc[oy][1][2] = fmaf(w1.z, a.w, acc[oy][1][2]);
                acc[oy][1][3] = fmaf(w1.w, a.w, acc[oy][1][3]);
                acc[oy][0][0] = fmaf(w2.x, a.z, acc[oy][0][0]);
                acc[oy][0][1] = fmaf(w2.y, a.z, acc[oy][0][1]);
                acc[oy][0][2] = fmaf(w2.z, a.z, acc[oy][0][2]);
                acc[oy][0][3] = fmaf(w2.w, a.z, acc[oy][0][3]);
                acc[oy][1][0] = fmaf(w2.x, e, acc[oy][1][0]);
                acc[oy][1][1] = fmaf(w2.y, e, acc[oy][1][1]);
                acc[oy][1][2] = fmaf(w2.z, e, acc[oy][1][2]);
                acc[oy][1][3] = fmaf(w2.w, e, acc[oy][1][3]);
            }
        }
    }

    // epilogue: fp16 stores + per-channel stats
    float lsum[4] = {0.f,0.f,0.f,0.f};
    float lsq [4] = {0.f,0.f,0.f,0.f};
    if (active) {
        #pragma unroll
        for (int oy = 0; oy < 2; ++oy) {
            const int OY = 2*rt + oy;
            #pragma unroll
            for (int c = 0; c < 4; ++c) {
                float v0 = acc[oy][0][c];
                float v1 = acc[oy][1][c];
                __half2* d = (__half2*)(g_yh + ((size_t)(b*CO + cbase + c)*OH + OY)*OW);
                d[(c0>>1) + lane] = __floats2half2_rn(v0, v1);
                lsum[c] += v0 + v1;
                lsq [c] += v0*v0 + v1*v1;
            }
        }
    }
    #pragma unroll
    for (int c = 0; c < 4; ++c) {
        float s = lsum[c], q = lsq[c];
        #pragma unroll
        for (int o = 16; o > 0; o >>= 1) {
            s += __shfl_xor_sync(0xffffffffu, s, o);
            q += __shfl_xor_sync(0xffffffffu, q, o);
        }
        if (lane == 0) {
            atomicAdd(&g_sum[cbase + c], s);
            atomicAdd(&g_sq [cbase + c], q);
        }
    }
}

// ---------------------------------------------------------------------------
// Computes scale/shift, then re-zeroes accumulators for the next graph replay.
__global__ void finalize_stats_kernel(const float* __restrict__ gamma,
                                      const float* __restrict__ beta) {
    int c = threadIdx.x;
    if (c >= CO) return;
    float invN  = 1.0f / (float)NPC;
    float mean  = g_sum[c] * invN;
    float var   = g_sq[c] * invN - mean*mean;
    float inv   = rsqrtf(var + 1e-5f);
    float scale = gamma[c] * inv;
    g_scale[c]  = scale;
    g_shift[c]  = beta[c] - mean*scale;
    g_sum[c] = 0.f;
    g_sq [c] = 0.f;
}

// ---------------------------------------------------------------------------
// BN + GELU + MaxPool via GELU unimodality:
//   max_w gelu(affine(y)) = max(gelu(affine(min_w y)), gelu(affine(max_w y)))
// smem holds RAW fp16 y with NaN halo (hmin/hmax drop NaN). half2 vertical
// reduction; 2 erf evals per OUTPUT.
#define POOL_THREADS 224
#define PPITCH 136                // halves; interior col c at idx c+8
#define PROWS  113                // rows -1..111
#define PPLANE (PROWS*PPITCH)     // 15368 halves = 30736 B

__global__ __launch_bounds__(POOL_THREADS)
void bn_gelu_pool_kernel(float* __restrict__ out) {
    extern __shared__ __half sH[];
    const int c = blockIdx.x;
    const int b = blockIdx.y;
    const int tid = threadIdx.x;

    const __half NH = __ushort_as_half((unsigned short)0x7e00);  // NaN
    if (tid < PPITCH) sH[tid] = NH;                   // top halo row
    for (int i = tid; i < OH; i += POOL_THREADS) {    // left halo (idx 6,7)
        sH[(i+1)*PPITCH + 6] = NH;
        sH[(i+1)*PPITCH + 7] = NH;
    }

    // phase 1: raw copy gmem fp16 -> padded smem (float4 = 8 halves)
    const int k  = tid % 14;
    const int r0 = tid / 14;
    const float4* yv = (const float4*)(g_yh + (size_t)(b*CO + c)*(OH*OW));
    for (int r = r0; r < OH; r += 16) {
        float4 p = yv[r*14 + k];
        *(float4*)&sH[(r+1)*PPITCH + 8 + 8*k] = p;
    }
    __syncthreads();

    const float scale = g_scale[c];
    const float shift = g_shift[c];

    // phase 2: half2 vertical min/max over 3 rows, scalar window combine,
    // 2 gelu evals per output.
    const int g  = tid % 14;          // px group 4g..4g+3
    const int ty = tid / 14;
    float* op = &out[(size_t)(b*CO + c)*(PH*PW)];
    for (int py = ty; py < PH; py += 16) {
        const __half2* q0 = (const __half2*)&sH[(2*py)*PPITCH + 8*g + 6];
        const __half2* q1 = (const __half2*)((const __half*)q0 + PPITCH);
        const __half2* q2 = (const __half2*)((const __half*)q1 + PPITCH);
        __half2 vmin[5], vmax[5];
        #pragma unroll
        for (int j = 0; j < 5; ++j) {
            __half2 a = q0[j], bb = q1[j], cc = q2[j];
            vmax[j] = __hmax2(__hmax2(a, bb), cc);
            vmin[j] = __hmin2(__hmin2(a, bb), cc);
        }
        const __half* Hm = (const __half*)vmin;
        const __half* HM = (const __half*)vmax;
        float4 o;
        float* ov = (float*)&o;
        #pragma unroll
        for (int j = 0; j < 4; ++j) {
            __half wm = __hmin(Hm[2*j+1], __hmin(Hm[2*j+2], Hm[2*j+3]));
            __half wM = __hmax(HM[2*j+1], __hmax(HM[2*j+2], HM[2*j+3]));
            float a1 = fmaf(__half2float(wm), scale, shift);
            float a2 = fmaf(__half2float(wM), scale, shift);
            float g1 = 0.5f*a1*(1.0f + erff(a1*0.70710678118654752f));
            float g2 = 0.5f*a2*(1.0f + erff(a2*0.70710678118654752f));
            ov[j] = fmaxf(g1, g2);
        }
        *(float4*)&op[py*PW + 4*g] = o;
    }
}

// ---------------------------------------------------------------------------
extern "C" void kernel_launch(void* const* d_in, const int* in_sizes, int n_in,
                              void* d_out, int out_size) {
    const float* x      = (const float*)d_in[0];
    const float* conv_w = (const float*)d_in[1];
    const float* conv_b = (const float*)d_in[2];
    const float* gamma  = (const float*)d_in[3];
    const float* beta   = (const float*)d_in[4];
    float* out = (float*)d_out;

    const int conv_smem = (SIN_SZ + SW_SZ) * sizeof(float);  // 11376 B
    const int pool_smem = PPLANE * sizeof(__half);           // 30736 B
    cudaFuncSetAttribute(conv_stats_kernel,
                         cudaFuncAttributeMaxDynamicSharedMemorySize, conv_smem);
    cudaFuncSetAttribute(bn_gelu_pool_kernel,
                         cudaFuncAttributeMaxDynamicSharedMemorySize, pool_smem);

    conv_stats_kernel<<<dim3(112, B_, 6), CONV_THREADS, conv_smem>>>(x, conv_w, conv_b);
    finalize_stats_kernel<<<1, CO>>>(gamma, beta);
    bn_gelu_pool_kernel<<<dim3(CO, B_), POOL_THREADS, pool_smem>>>(out);
}

// round 6
// speedup vs baseline: 2.9203x; 2.9203x over previous
#include <cuda_runtime.h>
#include <cuda_fp16.h>
#include <math.h>
#include <stdint.h>

#define B_    32
#define CIN   3
#define HIN   224
#define WIN   224
#define CO    192
#define OH    112
#define OW    112
#define PH    56
#define PW    56
#define NPC   (B_*OH*OW)   // 401408

// -------- device scratch ----------------------------------------------------
__device__ __half g_yh[(size_t)B_*CO*OH*OW];   // conv output fp16, ~154 MB
__device__ float g_sum[CO];                    // zeroed at load; finalize re-zeroes
__device__ float g_sq[CO];
__device__ float g_scale[CO];
__device__ float g_shift[CO];

// ---------------------------------------------------------------------------
__device__ __forceinline__ void mma16816(float& d0, float& d1, float& d2, float& d3,
                                         uint32_t a0, uint32_t a1, uint32_t a2, uint32_t a3,
                                         uint32_t b0, uint32_t b1) {
    asm volatile(
        "mma.sync.aligned.m16n8k16.row.col.f32.f16.f16.f32 "
        "{%0,%1,%2,%3},{%4,%5,%6,%7},{%8,%9},{%0,%1,%2,%3};"
        : "+f"(d0), "+f"(d1), "+f"(d2), "+f"(d3)
        : "r"(a0), "r"(a1), "r"(a2), "r"(a3), "r"(b0), "r"(b1));
}

// ---------------------------------------------------------------------------
// Implicit-GEMM conv via tensor cores.
// Block (448 thr = 14 warps) computes one (b, oy): all 192 channels x 112 cols.
// A = weights [192 x 32] fp16 (taps 27..31 zero), pitch 40 halves.
// B = im2col  [112 x 32] fp16 (n-major so (k,k+1) pairs are adjacent), pitch 40.
// Warp w: mh = w&1 -> m-tiles mh*6..+5 (96 ch); ng = w>>1 -> cols ng*16..+15.
#define CONV_THREADS 448
#define APITCH 40
#define BPITCH 40
#define XPITCH 232
// smem halves layout
#define A_OFF  0                       // 192*40      = 7680 halves
#define B_OFF  (192*APITCH)            // 112*40      = 4480 halves
#define X_OFF  (B_OFF + OW*BPITCH)     // 9*232       = 2088 halves
#define H_TOT  (X_OFF + 9*XPITCH)      // 14248 halves (even)
#define F_BIAS 0                       // floats after halves
#define F_SUM  192
#define F_SQ   384
#define CONV_SMEM (H_TOT*2 + 576*4)    // 28496 + 2304 = 30800 B

__global__ __launch_bounds__(CONV_THREADS, 2)
void conv_mma_kernel(const float* __restrict__ x,
                     const float* __restrict__ conv_w,
                     const float* __restrict__ conv_b) {
    extern __shared__ __half sm[];
    __half* A_s = sm + A_OFF;
    __half* B_s = sm + B_OFF;
    __half* sX  = sm + X_OFF;
    float*  sBias = (float*)(sm + H_TOT);
    float*  sSum  = sBias + F_SUM  - 0 + 0;   // sBias[192] then sums
    sSum = sBias + 192;
    float*  sSq   = sBias + 384;

    const int tid  = threadIdx.x;
    const int lane = tid & 31;
    const int w    = tid >> 5;
    const int oy   = blockIdx.x;
    const int b    = blockIdx.y;

    // ---- stats/bias init ----
    if (tid < 192) {
        sBias[tid] = conv_b[tid];
        sSum[tid] = 0.f;
        sSq [tid] = 0.f;
    }

    // ---- stage 9 input rows (3ci x 3ky) as fp16, cols -1..224 ----
    {
        const int gr_base = 2*oy - 1;
        for (int i = tid; i < 9*226; i += CONV_THREADS) {
            int r9 = i / 226;
            int c  = i - r9*226;
            int ci = r9 / 3;
            int ky = r9 - ci*3;
            int gr = gr_base + ky;
            int gc = c - 1;
            float v = 0.f;
            if (gr >= 0 && gr < HIN && gc >= 0 && gc < WIN)
                v = x[((size_t)(b*CIN + ci)*HIN + gr)*WIN + gc];
            sX[r9*XPITCH + c] = __float2half(v);
        }
    }

    // ---- build A (weights) [192][40], taps 27..31 zero ----
    for (int i = tid; i < 192*32; i += CONV_THREADS) {
        int co = i >> 5;
        int k  = i & 31;
        float v = (k < 27) ? conv_w[co*27 + k] : 0.f;
        A_s[co*APITCH + k] = __float2half(v);
    }
    __syncthreads();   // sX ready before B build

    // ---- build B (im2col) [112 n][40 k] from staged rows ----
    for (int i = tid; i < 112*32; i += CONV_THREADS) {
        int k = i / 112;
        int n = i - k*112;
        __half v = __float2half(0.f);
        if (k < 27) {
            int ci = k / 9;
            int r  = k - ci*9;
            int ky = r / 3;
            int kx = r - ky*3;
            v = sX[(ci*3 + ky)*XPITCH + 2*n + kx];
        }
        B_s[n*BPITCH + k] = v;
    }
    __syncthreads();

    // ---- MMA mainloop ----
    const int mh = w & 1;
    const int ng = w >> 1;
    const int qr = lane >> 2;          // 0..7  (row/group id)
    const int qc = lane & 3;           // 0..3

    float acc[6][2][4];
    #pragma unroll
    for (int mi = 0; mi < 6; ++mi)
        #pragma unroll
        for (int ni = 0; ni < 2; ++ni)
            #pragma unroll
            for (int j = 0; j < 4; ++j) acc[mi][ni][j] = 0.f;

    #pragma unroll
    for (int ks = 0; ks < 2; ++ks) {
        const int kb = ks*16 + 2*qc;
        uint32_t bf[2][2];
        #pragma unroll
        for (int ni = 0; ni < 2; ++ni) {
            const __half* bp = &B_s[(ng*16 + ni*8 + qr)*BPITCH + kb];
            bf[ni][0] = *(const uint32_t*)(bp);
            bf[ni][1] = *(const uint32_t*)(bp + 8);
        }
        #pragma unroll
        for (int mi = 0; mi < 6; ++mi) {
            const int R = (mh*6 + mi)*16 + qr;
            const __half* ap = &A_s[R*APITCH + kb];
            uint32_t a0 = *(const uint32_t*)(ap);
            uint32_t a1 = *(const uint32_t*)(ap + 8*APITCH);
            uint32_t a2 = *(const uint32_t*)(ap + 8);
            uint32_t a3 = *(const uint32_t*)(ap + 8*APITCH + 8);
            #pragma unroll
            for (int ni = 0; ni < 2; ++ni)
                mma16816(acc[mi][ni][0], acc[mi][ni][1], acc[mi][ni][2], acc[mi][ni][3],
                         a0, a1, a2, a3, bf[ni][0], bf[ni][1]);
        }
    }

    // ---- epilogue: bias, fp16 store, stats ----
    #pragma unroll
    for (int mi = 0; mi < 6; ++mi) {
        const int R0 = (mh*6 + mi)*16 + qr;
        const int R8 = R0 + 8;
        const float bias0 = sBias[R0];
        const float bias8 = sBias[R8];
        float s0 = 0.f, q0 = 0.f, s8 = 0.f, q8 = 0.f;
        #pragma unroll
        for (int ni = 0; ni < 2; ++ni) {
            const int C = ng*16 + ni*8 + 2*qc;
            float v0 = acc[mi][ni][0] + bias0;
            float v1 = acc[mi][ni][1] + bias0;
            float v2 = acc[mi][ni][2] + bias8;
            float v3 = acc[mi][ni][3] + bias8;
            __half2* d0 = (__half2*)(g_yh + ((size_t)(b*CO + R0)*OH + oy)*OW + C);
            __half2* d8 = (__half2*)(g_yh + ((size_t)(b*CO + R8)*OH + oy)*OW + C);
            *d0 = __floats2half2_rn(v0, v1);
            *d8 = __floats2half2_rn(v2, v3);
            s0 += v0 + v1;  q0 += v0*v0 + v1*v1;
            s8 += v2 + v3;  q8 += v2*v2 + v3*v3;
        }
        // reduce across the 4 lanes sharing this row (lane%4 group)
        #pragma unroll
        for (int o = 1; o <= 2; o <<= 1) {
            s0 += __shfl_xor_sync(0xffffffffu, s0, o);
            q0 += __shfl_xor_sync(0xffffffffu, q0, o);
            s8 += __shfl_xor_sync(0xffffffffu, s8, o);
            q8 += __shfl_xor_sync(0xffffffffu, q8, o);
        }
        if (qc == 0) {
            atomicAdd(&sSum[R0], s0);
            atomicAdd(&sSq [R0], q0);
            atomicAdd(&sSum[R8], s8);
            atomicAdd(&sSq [R8], q8);
        }
    }
    __syncthreads();
    if (tid < 192) {
        atomicAdd(&g_sum[tid], sSum[tid]);
        atomicAdd(&g_sq [tid], sSq [tid]);
    }
}

// ---------------------------------------------------------------------------
__global__ void finalize_stats_kernel(const float* __restrict__ gamma,
                                      const float* __restrict__ beta) {
    int c = threadIdx.x;
    if (c >= CO) return;
    float invN  = 1.0f / (float)NPC;
    float mean  = g_sum[c] * invN;
    float var   = g_sq[c] * invN - mean*mean;
    float inv   = rsqrtf(var + 1e-5f);
    float scale = gamma[c] * inv;
    g_scale[c]  = scale;
    g_shift[c]  = beta[c] - mean*scale;
    g_sum[c] = 0.f;   // re-zero for next graph replay
    g_sq [c] = 0.f;
}

// ---------------------------------------------------------------------------
// BN + GELU + MaxPool via GELU unimodality:
//   max_w gelu(affine(y)) = max(gelu(affine(min_w y)), gelu(affine(max_w y)))
#define POOL_THREADS 224
#define PPITCH 136
#define PROWS  113
#define PPLANE (PROWS*PPITCH)

__global__ __launch_bounds__(POOL_THREADS)
void bn_gelu_pool_kernel(float* __restrict__ out) {
    extern __shared__ __half sH[];
    const int c = blockIdx.x;
    const int b = blockIdx.y;
    const int tid = threadIdx.x;

    const __half NH = __ushort_as_half((unsigned short)0x7e00);  // NaN
    if (tid < PPITCH) sH[tid] = NH;
    for (int i = tid; i < OH; i += POOL_THREADS) {
        sH[(i+1)*PPITCH + 6] = NH;
        sH[(i+1)*PPITCH + 7] = NH;
    }

    const int k  = tid % 14;
    const int r0 = tid / 14;
    const float4* yv = (const float4*)(g_yh + (size_t)(b*CO + c)*(OH*OW));
    for (int r = r0; r < OH; r += 16) {
        float4 p = yv[r*14 + k];
        *(float4*)&sH[(r+1)*PPITCH + 8 + 8*k] = p;
    }
    __syncthreads();

    const float scale = g_scale[c];
    const float shift = g_shift[c];

    const int g  = tid % 14;
    const int ty = tid / 14;
    float* op = &out[(size_t)(b*CO + c)*(PH*PW)];
    for (int py = ty; py < PH; py += 16) {
        const __half2* q0 = (const __half2*)&sH[(2*py)*PPITCH + 8*g + 6];
        const __half2* q1 = (const __half2*)((const __half*)q0 + PPITCH);
        const __half2* q2 = (const __half2*)((const __half*)q1 + PPITCH);
        __half2 vmin[5], vmax[5];
        #pragma unroll
        for (int j = 0; j < 5; ++j) {
            __half2 a = q0[j], bb = q1[j], cc = q2[j];
            vmax[j] = __hmax2(__hmax2(a, bb), cc);
            vmin[j] = __hmin2(__hmin2(a, bb), cc);
        }
        const __half* Hm = (const __half*)vmin;
        const __half* HM = (const __half*)vmax;
        float4 o;
        float* ov = (float*)&o;
        #pragma unroll
        for (int j = 0; j < 4; ++j) {
            __half wm = __hmin(Hm[2*j+1], __hmin(Hm[2*j+2], Hm[2*j+3]));
            __half wM = __hmax(HM[2*j+1], __hmax(HM[2*j+2], HM[2*j+3]));
            float a1 = fmaf(__half2float(wm), scale, shift);
            float a2 = fmaf(__half2float(wM), scale, shift);
            float g1 = 0.5f*a1*(1.0f + erff(a1*0.70710678118654752f));
            float g2 = 0.5f*a2*(1.0f + erff(a2*0.70710678118654752f));
            ov[j] = fmaxf(g1, g2);
        }
        *(float4*)&op[py*PW + 4*g] = o;
    }
}

// ---------------------------------------------------------------------------
extern "C" void kernel_launch(void* const* d_in, const int* in_sizes, int n_in,
                              void* d_out, int out_size) {
    const float* x      = (const float*)d_in[0];
    const float* conv_w = (const float*)d_in[1];
    const float* conv_b = (const float*)d_in[2];
    const float* gamma  = (const float*)d_in[3];
    const float* beta   = (const float*)d_in[4];
    float* out = (float*)d_out;

    const int pool_smem = PPLANE * sizeof(__half);
    cudaFuncSetAttribute(conv_mma_kernel,
                         cudaFuncAttributeMaxDynamicSharedMemorySize, CONV_SMEM);
    cudaFuncSetAttribute(bn_gelu_pool_kernel,
                         cudaFuncAttributeMaxDynamicSharedMemorySize, pool_smem);

    conv_mma_kernel<<<dim3(OH, B_), CONV_THREADS, CONV_SMEM>>>(x, conv_w, conv_b);
    finalize_stats_kernel<<<1, CO>>>(gamma, beta);
    bn_gelu_pool_kernel<<<dim3(CO, B_), POOL_THREADS, pool_smem>>>(out);
}